// round 8
// baseline (speedup 1.0000x reference)
#include <cuda_runtime.h>
#include <math.h>

// Problem dims (fixed by the reference setup)
#define NB 4096
#define NT 512
#define NS 6
#define NF 12
#define NW (NB / 32)          // 128 batch-groups (one warp-group of work each)
#define WROW 192              // floats per (group, t) slice in g_v = 32 lanes * 6

__device__ float    g_v[NW * NT * WROW];           // Viterbi values [w][t][lane][s]
__device__ unsigned g_bp[NW * NT * 32];            // packed backpointers [w][t][lane]
__device__ int      g_last[NB];                    // argmax state at t=511
__device__ float    g_logtrans[NS * NS];           // [p][s]
__device__ float    g_loginit[NS];
__device__ float    g_epar[2 * NS * NF + 2 * NS];  // inv2[72], mu*inv2[72], c[6], logdet[6]

#define V_W (NT * WROW)       // per-group stride in g_v

// SMEM ring geometry for the fused kernel
#define SLICE_W  194          // padded slice row (words); even -> float2-aligned
#define CHUNK_T  32           // t-slices per chunk
#define RING_CH  8            // chunks resident in the ring
#define CHUNK_W  (CHUNK_T * SLICE_W)
#define N_CHUNKS (NT / CHUNK_T)          // 16
#define RING_BYTES (RING_CH * CHUNK_W * 4)   // 198656 B

// ---------------------------------------------------------------------------
// K0: parameter precompute, thread-parallel.
// ---------------------------------------------------------------------------
__global__ void k_setup(const float* __restrict__ trans,
                        const float* __restrict__ init,
                        const float* __restrict__ means,
                        const float* __restrict__ logsc)
{
    int tid = threadIdx.x;

    if (tid < 36) {                       // g_logtrans[p][s]
        int p = tid / 6, s = tid - p * 6;
        float m = trans[p * 6 + 0];
#pragma unroll
        for (int k = 1; k < 6; k++) m = fmaxf(m, trans[p * 6 + k]);
        float sum = 0.f;
#pragma unroll
        for (int k = 0; k < 6; k++) sum += expf(trans[p * 6 + k] - m);
        g_logtrans[tid] = logf(expf(trans[p * 6 + s] - m) / sum + 1e-8f);
    }
    if (tid >= 36 && tid < 42) {          // g_loginit[s]
        int s = tid - 36;
        float m = init[0];
#pragma unroll
        for (int k = 1; k < 6; k++) m = fmaxf(m, init[k]);
        float sum = 0.f;
#pragma unroll
        for (int k = 0; k < 6; k++) sum += expf(init[k] - m);
        g_loginit[s] = logf(expf(init[s] - m) / sum + 1e-8f);
    }
    if (tid >= 64 && tid < 136) {         // per-(s,f) inv2 and mu*inv2
        int idx = tid - 64;
        int s = idx / 12, f = idx - s * 12;
        float x    = logsc[s * 12 + f];
        float sc   = log1pf(expf(x)) + 1e-6f;
        float den  = sc + 1e-6f;
        float inv2 = 1.0f / (den * den);
        float mu   = means[s * 12 + f];
        g_epar[s * 12 + f]      = inv2;
        g_epar[72 + s * 12 + f] = mu * inv2;
    }
    if (tid >= 136 && tid < 142) {        // per-s c and logdet
        int s = tid - 136;
        float c = 0.f, ld = 0.f;
#pragma unroll
        for (int f = 0; f < 12; f++) {
            float x    = logsc[s * 12 + f];
            float sc   = log1pf(expf(x)) + 1e-6f;
            float den  = sc + 1e-6f;
            float inv2 = 1.0f / (den * den);
            float mu   = means[s * 12 + f];
            c  += mu * mu * inv2;
            ld += logf(sc);
        }
        g_epar[144 + s] = c;
        g_epar[150 + s] = ld;
    }
}

// ---------------------------------------------------------------------------
// K1: FUSED emission + forward Viterbi. One 128-thread block per batch-group.
// Warps 0-2: producers — compute emission logp from obs straight into a
//            shared-memory ring (8 chunks x 32 t-slices x 194 words).
// Warp 3:    consumer — serial DP over t, reading slices from the ring with
//            depth-2 register lookahead, writing v_t to g_v.
// Sync: per-chunk atomic counters (producer->consumer) + a consumed counter
// (consumer->producer, ring-space backpressure, invariant consumed >= c-7).
// ---------------------------------------------------------------------------
__global__ void __launch_bounds__(128, 1)
k_fused(const float* __restrict__ obs, float* __restrict__ out,
        int write_score, int score_off)
{
    extern __shared__ float ring[];
    __shared__ float sp[156];
    __shared__ int   prod_cnt[N_CHUNKS];
    __shared__ int   consumed;

    int tid  = threadIdx.x;
    int lane = tid & 31;
    int wid  = tid >> 5;
    int w    = blockIdx.x;

    for (int i = tid; i < 156; i += 128) sp[i] = g_epar[i];   // FIX: full 156 loads
    if (tid < N_CHUNKS) prod_cnt[tid] = 0;
    if (tid == 0) consumed = 0;
    __syncthreads();

    if (wid < 3) {
        // ---------------- producers ----------------
        const float* ob = obs + (size_t)w * 32 * NT * NF;
#pragma unroll 1
        for (int c = 0; c < N_CHUNKS; c++) {
            if (c >= RING_CH) {   // backpressure: slot (c&7) free iff consumed >= c-7
                while (*(volatile int*)&consumed < c - (RING_CH - 1)) { }
                __threadfence_block();
            }
            float* slot = ring + (size_t)(c & (RING_CH - 1)) * CHUNK_W;
            int t0 = c * CHUNK_T;
#pragma unroll 1
            for (int i = 0; i < 11; i++) {
                int site = wid * 32 + lane + 96 * i;   // warp covers one aligned 32-site group
                if (site < 1024) {
                    int b  = site >> 5;                // batch lane within group
                    int tt = site & 31;                // t within chunk
                    const float4* op = (const float4*)(ob + ((size_t)b * NT + t0 + tt) * NF);
                    float4 o0 = __ldcs(op), o1 = __ldcs(op + 1), o2v = __ldcs(op + 2);
                    float o[12] = { o0.x, o0.y, o0.z, o0.w, o1.x, o1.y, o1.z, o1.w,
                                    o2v.x, o2v.y, o2v.z, o2v.w };
                    float osq[12];
#pragma unroll
                    for (int f = 0; f < 12; f++) osq[f] = o[f] * o[f];
                    float e[6];
#pragma unroll
                    for (int s = 0; s < NS; s++) {
                        float a1 = 0.f, a2 = 0.f;
#pragma unroll
                        for (int f = 0; f < 12; f++) {
                            a1 = fmaf(osq[f], sp[s * 12 + f], a1);
                            a2 = fmaf(o[f],   sp[72 + s * 12 + f], a2);
                        }
                        e[s] = -0.5f * (a1 - 2.f * a2 + sp[144 + s]) - sp[150 + s];
                    }
                    float2* d = (float2*)(slot + tt * SLICE_W + b * 6);
                    d[0] = make_float2(e[0], e[1]);
                    d[1] = make_float2(e[2], e[3]);
                    d[2] = make_float2(e[4], e[5]);
                }
            }
            __syncwarp();
            __threadfence_block();
            if (lane == 0) atomicAdd(&prod_cnt[c], 1);
        }
    } else {
        // ---------------- consumer (DP warp, own SMSP) ----------------
        float lt[36];
#pragma unroll
        for (int i = 0; i < 36; i++) lt[i] = g_logtrans[i];

        float* pv = g_v + (size_t)w * V_W + lane * 6;

#define LOAD_SLICE(E, T) do {                                                 \
        const float2* q_ = (const float2*)(ring +                             \
            (size_t)(((T) >> 5) & (RING_CH - 1)) * CHUNK_W +                  \
            ((T) & 31) * SLICE_W + lane * 6);                                 \
        float2 a_ = q_[0], b_ = q_[1], c_ = q_[2];                            \
        E[0] = a_.x; E[1] = a_.y; E[2] = b_.x;                                \
        E[3] = b_.y; E[4] = c_.x; E[5] = c_.y; } while (0)

        // wait chunk 0, then init with slice 0
        while (*(volatile int*)&prod_cnt[0] < 3) { }
        __threadfence_block();

        float e[6], eN[6], v[6];
        LOAD_SLICE(e, 0);
#pragma unroll
        for (int s = 0; s < 6; s++) v[s] = g_loginit[s] + e[s];
        {
            float2* wr = (float2*)pv;
            wr[0] = make_float2(v[0], v[1]);
            wr[1] = make_float2(v[2], v[3]);
            wr[2] = make_float2(v[4], v[5]);
        }
        LOAD_SLICE(e, 1);      // slice for t=1
        LOAD_SLICE(eN, 2);     // slice for t=2 (both in chunk 0)

#pragma unroll 4
        for (int t = 1; t <= 511; t++) {
            float nv[6];
            nv[0] = fmaxf(fmaxf(fmaxf(v[0]+lt[0],  v[1]+lt[6]),
                                fmaxf(v[2]+lt[12], v[3]+lt[18])),
                          fmaxf(v[4]+lt[24], v[5]+lt[30])) + e[0];
            nv[1] = fmaxf(fmaxf(fmaxf(v[0]+lt[1],  v[1]+lt[7]),
                                fmaxf(v[2]+lt[13], v[3]+lt[19])),
                          fmaxf(v[4]+lt[25], v[5]+lt[31])) + e[1];
            nv[2] = fmaxf(fmaxf(fmaxf(v[0]+lt[2],  v[1]+lt[8]),
                                fmaxf(v[2]+lt[14], v[3]+lt[20])),
                          fmaxf(v[4]+lt[26], v[5]+lt[32])) + e[2];
            nv[3] = fmaxf(fmaxf(fmaxf(v[0]+lt[3],  v[1]+lt[9]),
                                fmaxf(v[2]+lt[15], v[3]+lt[21])),
                          fmaxf(v[4]+lt[27], v[5]+lt[33])) + e[3];
            nv[4] = fmaxf(fmaxf(fmaxf(v[0]+lt[4],  v[1]+lt[10]),
                                fmaxf(v[2]+lt[16], v[3]+lt[22])),
                          fmaxf(v[4]+lt[28], v[5]+lt[34])) + e[4];
            nv[5] = fmaxf(fmaxf(fmaxf(v[0]+lt[5],  v[1]+lt[11]),
                                fmaxf(v[2]+lt[17], v[3]+lt[23])),
                          fmaxf(v[4]+lt[29], v[5]+lt[35])) + e[5];
#pragma unroll
            for (int s = 0; s < 6; s++) v[s] = nv[s];
            {
                float2* wr = (float2*)(pv + (size_t)t * WROW);
                wr[0] = make_float2(v[0], v[1]);
                wr[1] = make_float2(v[2], v[3]);
                wr[2] = make_float2(v[4], v[5]);
            }
            // shift lookahead and preload slice t+2
#pragma unroll
            for (int s = 0; s < 6; s++) e[s] = eN[s];
            int tn = t + 2;
            if (tn <= 511) {
                if ((tn & 31) == 0) {
                    int c = tn >> 5;
                    __syncwarp();
                    __threadfence_block();
                    if (lane == 0) *(volatile int*)&consumed = c;  // chunks 0..c-1 drained
                    while (*(volatile int*)&prod_cnt[c] < 3) { }
                    __threadfence_block();
                }
                LOAD_SLICE(eN, tn);
            }
        }

        // final state / score (first-argmax, strict >)
        float m = v[0]; int idx = 0;
#pragma unroll
        for (int s = 1; s < 6; s++) if (v[s] > m) { m = v[s]; idx = s; }
        int b = w * 32 + lane;
        g_last[b] = idx;
        if (write_score) out[score_off + b] = m;
    }
}

// ---------------------------------------------------------------------------
// K2: backpointers, fully parallel over (t, b). Reads v_{t-1} (coalesced
// 768B/warp, largely L2-resident now), packs 6 first-argmax nibbles.
// ---------------------------------------------------------------------------
__global__ void k_bp()
{
    int lane = threadIdx.x & 31;
    int tz   = threadIdx.x >> 5;              // 0..7
    int w    = blockIdx.x;
    int t    = blockIdx.y * 8 + tz + 1;       // 1..512
    if (t >= 512) return;

    float lt[36];
#pragma unroll
    for (int i = 0; i < 36; i++) lt[i] = g_logtrans[i];

    const float* pv = g_v + (size_t)w * V_W + (size_t)(t - 1) * WROW + lane * 6;
    float2 a   = *(const float2*)pv;
    float2 bb2 = *(const float2*)(pv + 2);
    float2 cc2 = *(const float2*)(pv + 4);
    float v0 = a.x, v1 = a.y, v2 = bb2.x, v3 = bb2.y, v4 = cc2.x, v5 = cc2.y;

    unsigned pk = 0;
#pragma unroll
    for (int s = 0; s < 6; s++) {
        float c0 = v0 + lt[s],      c1 = v1 + lt[6 + s],  c2 = v2 + lt[12 + s];
        float c3 = v3 + lt[18 + s], c4 = v4 + lt[24 + s], c5 = v5 + lt[30 + s];
        // first-argmax tree: later index wins only on strict >
        bool g01 = c1 > c0;  float m01 = g01 ? c1 : c0;  int i01 = g01 ? 1 : 0;
        bool g23 = c3 > c2;  float m23 = g23 ? c3 : c2;  int i23 = g23 ? 3 : 2;
        bool g45 = c5 > c4;  float m45 = g45 ? c5 : c4;  int i45 = g45 ? 5 : 4;
        bool gA  = m23 > m01; float mA = gA ? m23 : m01; int iA  = gA ? i23 : i01;
        bool gB  = m45 > mA;  int idx = gB ? i45 : iA;
        pk |= (unsigned)idx << (4 * s);
    }
    g_bp[(size_t)w * NT * 32 + (size_t)t * 32 + lane] = pk;
}

// ---------------------------------------------------------------------------
// K3: backtrace. bp stream is 128B/step contiguous per warp. Fully unrolled
// 32-step blocks with ping-pong register buffers (compile-time indices).
// ---------------------------------------------------------------------------
#define BWD_BLOCK(CUR, NXT, DO_PREF)                                        \
do {                                                                        \
    _Pragma("unroll")                                                       \
    for (int i = 0; i < 32; i++) {                                          \
        if (DO_PREF) NXT[i] = __ldg(bprow + (size_t)(tb - 32 - i) * 32);    \
        itile[lane * 33 + 31 - i] = cur;         /* path[tb - i] */         \
        cur = (CUR[i] >> (cur * 4)) & 7;         /* path[tb - i - 1] */     \
    }                                                                       \
    __syncwarp();                                                           \
    if (write_path) {                                                       \
        _Pragma("unroll 8")                                                 \
        for (int r = 0; r < 32; r++)                                        \
            out[(size_t)(b0 + r) * NT + (tb - 31) + lane] =                 \
                (float)itile[r * 33 + lane];                                \
    }                                                                       \
    __syncwarp();                                                           \
    tb -= 32;                                                               \
} while (0)

__global__ void __launch_bounds__(32, 1)
k_bwd(float* __restrict__ out, int write_path)
{
    __shared__ int itile[32 * 33];

    int lane = threadIdx.x;
    int w  = blockIdx.x;
    int b0 = w * 32;

    int cur = g_last[b0 + lane];
    const unsigned* bprow = g_bp + (size_t)w * NT * 32 + lane;

    unsigned buf[32], nbuf[32];
#pragma unroll
    for (int i = 0; i < 32; i++)
        buf[i] = __ldg(bprow + (size_t)(511 - i) * 32);

    int tb = 511;
    for (int blk = 0; blk < 16; blk += 2) {
        BWD_BLOCK(buf,  nbuf, 1);            // prefetch next block (always valid)
        BWD_BLOCK(nbuf, buf,  (blk < 14));
    }
    // note: final step reads bp row 0 (allocated, unused value) — harmless
}

// ---------------------------------------------------------------------------
extern "C" void kernel_launch(void* const* d_in, const int* in_sizes, int n_in,
                              void* d_out, int out_size)
{
    (void)in_sizes; (void)n_in;
    const float* obs  = (const float*)d_in[0];
    const float* tr   = (const float*)d_in[1];
    const float* ini  = (const float*)d_in[2];
    const float* mu   = (const float*)d_in[3];
    const float* lsc  = (const float*)d_in[4];
    float* out = (float*)d_out;

    const int PT = NB * NT;
    int write_path = 0, write_score = 0, score_off = 0;
    if (out_size >= PT + NB)      { write_path = 1; write_score = 1; score_off = PT; }
    else if (out_size >= PT)      { write_path = 1; }
    else                          { write_score = 1; score_off = 0; }

    cudaFuncSetAttribute(k_fused, cudaFuncAttributeMaxDynamicSharedMemorySize,
                         RING_BYTES);

    k_setup<<<1, 160>>>(tr, ini, mu, lsc);
    k_fused<<<NW, 128, RING_BYTES>>>(obs, out, write_score, score_off);
    k_bp<<<dim3(NW, 64), 256>>>();
    k_bwd<<<NW, 32>>>(out, write_path);
}

// round 9
// speedup vs baseline: 1.4903x; 1.4903x over previous
#include <cuda_runtime.h>
#include <math.h>

// Problem dims (fixed by the reference setup)
#define NB 4096
#define NT 512
#define NS 6
#define NF 12
#define NW (NB / 32)          // 128 batch-groups

__device__ unsigned g_bp[NW * NT * 32];            // packed backpointers [w][t][lane]
__device__ int      g_last[NB];                    // argmax state at t=511
__device__ float    g_logtrans[NS * NS];           // [p][s]
__device__ float    g_loginit[NS];
__device__ float    g_epar[2 * NS * NF + 2 * NS];  // inv2[72], mu*inv2[72], c[6], logdet[6]

// SMEM ring geometry
#define SLICE_W  194          // padded slice row (words); even -> float2-aligned
#define CHUNK_T  32           // t-slices per chunk
#define RING_CH  8            // chunks resident
#define CHUNK_W  (CHUNK_T * SLICE_W)
#define N_CHUNKS (NT / CHUNK_T)              // 16
#define RING_BYTES (RING_CH * CHUNK_W * 4)   // 198656 B

// ---------------------------------------------------------------------------
// K0: parameter precompute, thread-parallel.
// ---------------------------------------------------------------------------
__global__ void k_setup(const float* __restrict__ trans,
                        const float* __restrict__ init,
                        const float* __restrict__ means,
                        const float* __restrict__ logsc)
{
    int tid = threadIdx.x;

    if (tid < 36) {                       // g_logtrans[p][s]
        int p = tid / 6, s = tid - p * 6;
        float m = trans[p * 6 + 0];
#pragma unroll
        for (int k = 1; k < 6; k++) m = fmaxf(m, trans[p * 6 + k]);
        float sum = 0.f;
#pragma unroll
        for (int k = 0; k < 6; k++) sum += expf(trans[p * 6 + k] - m);
        g_logtrans[tid] = logf(expf(trans[p * 6 + s] - m) / sum + 1e-8f);
    }
    if (tid >= 36 && tid < 42) {          // g_loginit[s]
        int s = tid - 36;
        float m = init[0];
#pragma unroll
        for (int k = 1; k < 6; k++) m = fmaxf(m, init[k]);
        float sum = 0.f;
#pragma unroll
        for (int k = 0; k < 6; k++) sum += expf(init[k] - m);
        g_loginit[s] = logf(expf(init[s] - m) / sum + 1e-8f);
    }
    if (tid >= 64 && tid < 136) {         // per-(s,f) inv2 and mu*inv2
        int idx = tid - 64;
        int s = idx / 12, f = idx - s * 12;
        float x    = logsc[s * 12 + f];
        float sc   = log1pf(expf(x)) + 1e-6f;
        float den  = sc + 1e-6f;
        float inv2 = 1.0f / (den * den);
        float mu   = means[s * 12 + f];
        g_epar[s * 12 + f]      = inv2;
        g_epar[72 + s * 12 + f] = mu * inv2;
    }
    if (tid >= 136 && tid < 142) {        // per-s c and logdet
        int s = tid - 136;
        float c = 0.f, ld = 0.f;
#pragma unroll
        for (int f = 0; f < 12; f++) {
            float x    = logsc[s * 12 + f];
            float sc   = log1pf(expf(x)) + 1e-6f;
            float den  = sc + 1e-6f;
            float inv2 = 1.0f / (den * den);
            float mu   = means[s * 12 + f];
            c  += mu * mu * inv2;
            ld += logf(sc);
        }
        g_epar[144 + s] = c;
        g_epar[150 + s] = ld;
    }
}

// ---------------------------------------------------------------------------
// K1: FUSED emission + forward Viterbi + backpointer recompute.
// 192 threads (6 warps) per batch-group:
//   wid 0-2: emission producers (depth-3 software-pipelined obs loads)
//   wid 3:   serial DP consumer; writes v_t back into the ring IN PLACE
//   wid 4-5: bp workers; read v from ring, write packed bp to gmem
// Flags: prod_cnt[c] (3 producers) -> consumer; cons_flag -> bp workers;
//        bp_cnt[c] (2 workers) -> producers (ring-slot backpressure:
//        slot c-8 reusable iff bp chunk c-7 complete, since bp chunk c-7's
//        first slice reads the last v-slice of chunk c-8).
// ---------------------------------------------------------------------------
__global__ void __launch_bounds__(192, 1)
k_fused(const float* __restrict__ obs, float* __restrict__ out,
        int write_score, int score_off)
{
    extern __shared__ float ring[];
    __shared__ float sp[156];
    __shared__ int   prod_cnt[N_CHUNKS];
    __shared__ int   bp_cnt[N_CHUNKS];
    __shared__ int   cons_flag;

    int tid  = threadIdx.x;
    int lane = tid & 31;
    int wid  = tid >> 5;
    int w    = blockIdx.x;

    for (int i = tid; i < 156; i += 192) sp[i] = g_epar[i];
    if (tid < N_CHUNKS) { prod_cnt[tid] = 0; bp_cnt[tid] = 0; }
    if (tid == 0) cons_flag = 0;
    __syncthreads();

    if (wid < 3) {
        // ================= producers =================
        const float4* ob4 = (const float4*)(obs + (size_t)w * 32 * NT * NF);
        const int NV = (wid == 2) ? 10 : 11;   // warp-uniform iteration count

#pragma unroll 1
        for (int c = 0; c < N_CHUNKS; c++) {
            int t0 = c * CHUNK_T;

            // depth-3 pipeline: preload iterations 0..2 (gmem only — no ring
            // dependence, so issue BEFORE the backpressure wait)
            float4 pre[3][3];
#pragma unroll
            for (int k = 0; k < 3; k++) {
                int b_ = wid + 3 * k;
                const float4* op = ob4 + (size_t)(b_ * NT + t0 + lane) * 3;
                pre[k][0] = __ldcs(op); pre[k][1] = __ldcs(op + 1); pre[k][2] = __ldcs(op + 2);
            }

            if (c >= RING_CH) {   // slot (c&7) free iff bp chunk c-7 done
                while (*(volatile int*)&bp_cnt[c - (RING_CH - 1)] < 2) { }
                __threadfence_block();
            }
            float* slot = ring + (size_t)(c & (RING_CH - 1)) * CHUNK_W;

#pragma unroll
            for (int i = 0; i < 11; i++) {
                if (i < NV) {
                    int b_ = wid + 3 * i;            // batch index; tt = lane
                    float4 q0 = pre[i % 3][0], q1 = pre[i % 3][1], q2 = pre[i % 3][2];
                    if (i + 3 < NV) {                // prefetch iteration i+3
                        int bn = wid + 3 * (i + 3);
                        const float4* op = ob4 + (size_t)(bn * NT + t0 + lane) * 3;
                        pre[i % 3][0] = __ldcs(op);
                        pre[i % 3][1] = __ldcs(op + 1);
                        pre[i % 3][2] = __ldcs(op + 2);
                    }
                    float o[12] = { q0.x, q0.y, q0.z, q0.w, q1.x, q1.y, q1.z, q1.w,
                                    q2.x, q2.y, q2.z, q2.w };
                    float osq[12];
#pragma unroll
                    for (int f = 0; f < 12; f++) osq[f] = o[f] * o[f];
                    float e[6];
#pragma unroll
                    for (int s = 0; s < NS; s++) {
                        float a1 = 0.f, a2 = 0.f;
#pragma unroll
                        for (int f = 0; f < 12; f++) {
                            a1 = fmaf(osq[f], sp[s * 12 + f], a1);
                            a2 = fmaf(o[f],   sp[72 + s * 12 + f], a2);
                        }
                        e[s] = -0.5f * (a1 - 2.f * a2 + sp[144 + s]) - sp[150 + s];
                    }
                    float2* d = (float2*)(slot + lane * SLICE_W + b_ * 6);
                    d[0] = make_float2(e[0], e[1]);
                    d[1] = make_float2(e[2], e[3]);
                    d[2] = make_float2(e[4], e[5]);
                }
            }
            __syncwarp();
            __threadfence_block();
            if (lane == 0) atomicAdd(&prod_cnt[c], 1);
        }
    } else if (wid == 3) {
        // ================= consumer (DP warp, own SMSP) =================
        float lt[36];
#pragma unroll
        for (int i = 0; i < 36; i++) lt[i] = g_logtrans[i];

#define SLICE_PTR(T) (ring + (size_t)(((T) >> 5) & (RING_CH - 1)) * CHUNK_W + \
                      ((T) & 31) * SLICE_W + lane * 6)
#define LOAD_SLICE(E, T) do {                                                 \
        const float2* q_ = (const float2*)SLICE_PTR(T);                       \
        float2 a_ = q_[0], b_ = q_[1], c_ = q_[2];                            \
        E[0] = a_.x; E[1] = a_.y; E[2] = b_.x;                                \
        E[3] = b_.y; E[4] = c_.x; E[5] = c_.y; } while (0)
#define STORE_V(T) do {                                                       \
        float2* d_ = (float2*)SLICE_PTR(T);                                   \
        d_[0] = make_float2(v[0], v[1]);                                      \
        d_[1] = make_float2(v[2], v[3]);                                      \
        d_[2] = make_float2(v[4], v[5]); } while (0)

        while (*(volatile int*)&prod_cnt[0] < 3) { }
        __threadfence_block();

        float e[6], eN[6], v[6];
        LOAD_SLICE(e, 0);
#pragma unroll
        for (int s = 0; s < 6; s++) v[s] = g_loginit[s] + e[s];
        LOAD_SLICE(e, 1);
        LOAD_SLICE(eN, 2);
        STORE_V(0);                       // overwrite slice 0 with v_0

#pragma unroll 4
        for (int t = 1; t <= 511; t++) {
            float nv[6];
            nv[0] = fmaxf(fmaxf(fmaxf(v[0]+lt[0],  v[1]+lt[6]),
                                fmaxf(v[2]+lt[12], v[3]+lt[18])),
                          fmaxf(v[4]+lt[24], v[5]+lt[30])) + e[0];
            nv[1] = fmaxf(fmaxf(fmaxf(v[0]+lt[1],  v[1]+lt[7]),
                                fmaxf(v[2]+lt[13], v[3]+lt[19])),
                          fmaxf(v[4]+lt[25], v[5]+lt[31])) + e[1];
            nv[2] = fmaxf(fmaxf(fmaxf(v[0]+lt[2],  v[1]+lt[8]),
                                fmaxf(v[2]+lt[14], v[3]+lt[20])),
                          fmaxf(v[4]+lt[26], v[5]+lt[32])) + e[2];
            nv[3] = fmaxf(fmaxf(fmaxf(v[0]+lt[3],  v[1]+lt[9]),
                                fmaxf(v[2]+lt[15], v[3]+lt[21])),
                          fmaxf(v[4]+lt[27], v[5]+lt[33])) + e[3];
            nv[4] = fmaxf(fmaxf(fmaxf(v[0]+lt[4],  v[1]+lt[10]),
                                fmaxf(v[2]+lt[16], v[3]+lt[22])),
                          fmaxf(v[4]+lt[28], v[5]+lt[34])) + e[4];
            nv[5] = fmaxf(fmaxf(fmaxf(v[0]+lt[5],  v[1]+lt[11]),
                                fmaxf(v[2]+lt[17], v[3]+lt[23])),
                          fmaxf(v[4]+lt[29], v[5]+lt[35])) + e[5];
#pragma unroll
            for (int s = 0; s < 6; s++) v[s] = nv[s];
            STORE_V(t);                   // overwrite slice t with v_t

            if ((t & 31) == 31) {         // chunk (t>>5) fully converted to v
                __syncwarp();
                __threadfence_block();
                if (lane == 0) *(volatile int*)&cons_flag = (t >> 5) + 1;
            }
#pragma unroll
            for (int s = 0; s < 6; s++) e[s] = eN[s];
            int tn = t + 2;
            if (tn <= 511) {
                if ((tn & 31) == 0) {
                    int c = tn >> 5;
                    while (*(volatile int*)&prod_cnt[c] < 3) { }
                    __threadfence_block();
                }
                LOAD_SLICE(eN, tn);
            }
        }

        float m = v[0]; int idx = 0;
#pragma unroll
        for (int s = 1; s < 6; s++) if (v[s] > m) { m = v[s]; idx = s; }
        int b = w * 32 + lane;
        g_last[b] = idx;
        if (write_score) out[score_off + b] = m;
    } else {
        // ================= bp workers (wid 4: slices 0-15, wid 5: 16-31) ===
        float lt[36];
#pragma unroll
        for (int i = 0; i < 36; i++) lt[i] = g_logtrans[i];

        int half = wid - 4;
        unsigned* bpw = g_bp + (size_t)w * NT * 32 + lane;

#pragma unroll 1
        for (int c = 0; c < N_CHUNKS; c++) {
            while (*(volatile int*)&cons_flag < c + 1) { }
            __threadfence_block();

#pragma unroll 1
            for (int i = 0; i < 16; i++) {
                int t = c * 32 + half * 16 + i;
                if (t == 0) continue;                 // bp rows start at t=1
                int tp = t - 1;
                const float2* q = (const float2*)(ring +
                    (size_t)((tp >> 5) & (RING_CH - 1)) * CHUNK_W +
                    (tp & 31) * SLICE_W + lane * 6);
                float2 a = q[0], bq = q[1], cc = q[2];
                float v0 = a.x, v1 = a.y, v2 = bq.x, v3 = bq.y, v4 = cc.x, v5 = cc.y;

                unsigned pk = 0;
#pragma unroll
                for (int s = 0; s < 6; s++) {
                    float c0 = v0 + lt[s],      c1 = v1 + lt[6 + s],  c2 = v2 + lt[12 + s];
                    float c3 = v3 + lt[18 + s], c4 = v4 + lt[24 + s], c5 = v5 + lt[30 + s];
                    bool g01 = c1 > c0;  float m01 = g01 ? c1 : c0;  int i01 = g01 ? 1 : 0;
                    bool g23 = c3 > c2;  float m23 = g23 ? c3 : c2;  int i23 = g23 ? 3 : 2;
                    bool g45 = c5 > c4;  float m45 = g45 ? c5 : c4;  int i45 = g45 ? 5 : 4;
                    bool gA  = m23 > m01; float mA = gA ? m23 : m01; int iA = gA ? i23 : i01;
                    bool gB  = m45 > mA;  int idx = gB ? i45 : iA;
                    pk |= (unsigned)idx << (4 * s);
                }
                bpw[(size_t)t * 32] = pk;
            }
            __syncwarp();
            if (lane == 0) atomicAdd(&bp_cnt[c], 1);   // smem reads complete
        }
    }
}

// ---------------------------------------------------------------------------
// K2: backtrace over packed backpointers (unchanged from R6/R8: compile-time
// register ring, ping-pong 32-step blocks, coalesced staged path writes).
// ---------------------------------------------------------------------------
#define BWD_BLOCK(CUR, NXT, DO_PREF)                                        \
do {                                                                        \
    _Pragma("unroll")                                                       \
    for (int i = 0; i < 32; i++) {                                          \
        if (DO_PREF) NXT[i] = __ldg(bprow + (size_t)(tb - 32 - i) * 32);    \
        itile[lane * 33 + 31 - i] = cur;         /* path[tb - i] */         \
        cur = (CUR[i] >> (cur * 4)) & 7;         /* path[tb - i - 1] */     \
    }                                                                       \
    __syncwarp();                                                           \
    if (write_path) {                                                       \
        _Pragma("unroll 8")                                                 \
        for (int r = 0; r < 32; r++)                                        \
            out[(size_t)(b0 + r) * NT + (tb - 31) + lane] =                 \
                (float)itile[r * 33 + lane];                                \
    }                                                                       \
    __syncwarp();                                                           \
    tb -= 32;                                                               \
} while (0)

__global__ void __launch_bounds__(32, 1)
k_bwd(float* __restrict__ out, int write_path)
{
    __shared__ int itile[32 * 33];

    int lane = threadIdx.x;
    int w  = blockIdx.x;
    int b0 = w * 32;

    int cur = g_last[b0 + lane];
    const unsigned* bprow = g_bp + (size_t)w * NT * 32 + lane;

    unsigned buf[32], nbuf[32];
#pragma unroll
    for (int i = 0; i < 32; i++)
        buf[i] = __ldg(bprow + (size_t)(511 - i) * 32);

    int tb = 511;
    for (int blk = 0; blk < 16; blk += 2) {
        BWD_BLOCK(buf,  nbuf, 1);
        BWD_BLOCK(nbuf, buf,  (blk < 14));
    }
    // final step reads bp row 0 (allocated, unused value) — harmless
}

// ---------------------------------------------------------------------------
extern "C" void kernel_launch(void* const* d_in, const int* in_sizes, int n_in,
                              void* d_out, int out_size)
{
    (void)in_sizes; (void)n_in;
    const float* obs  = (const float*)d_in[0];
    const float* tr   = (const float*)d_in[1];
    const float* ini  = (const float*)d_in[2];
    const float* mu   = (const float*)d_in[3];
    const float* lsc  = (const float*)d_in[4];
    float* out = (float*)d_out;

    const int PT = NB * NT;
    int write_path = 0, write_score = 0, score_off = 0;
    if (out_size >= PT + NB)      { write_path = 1; write_score = 1; score_off = PT; }
    else if (out_size >= PT)      { write_path = 1; }
    else                          { write_score = 1; score_off = 0; }

    cudaFuncSetAttribute(k_fused, cudaFuncAttributeMaxDynamicSharedMemorySize,
                         RING_BYTES);

    k_setup<<<1, 160>>>(tr, ini, mu, lsc);
    k_fused<<<NW, 192, RING_BYTES>>>(obs, out, write_score, score_off);
    k_bwd<<<NW, 32>>>(out, write_path);
}

// round 10
// speedup vs baseline: 1.5535x; 1.0424x over previous
#include <cuda_runtime.h>
#include <math.h>

// Problem dims (fixed by the reference setup)
#define NB 4096
#define NT 512
#define NS 6
#define NF 12
#define NW (NB / 32)          // 128 batch-groups

__device__ unsigned g_bp[NW * NT * 32];   // packed backpointers [w][t][lane]

// SMEM ring geometry
#define SLICE_W  194          // padded slice row (words); even -> float2-aligned
#define CHUNK_T  32
#define RING_CH  8
#define CHUNK_W  (CHUNK_T * SLICE_W)
#define N_CHUNKS (NT / CHUNK_T)              // 16
#define RING_BYTES (RING_CH * CHUNK_W * 4)   // 198656 B

// One DP step: read e(t) from ring at P (compile-time offset), update v in
// registers, overwrite the slice with v_t. Numerical order identical to R6-R9.
#define DP_STEP(P) do {                                                       \
    const float2* q_ = (const float2*)(P);                                    \
    float2 a_ = q_[0], b_ = q_[1], c_ = q_[2];                                \
    float e0=a_.x, e1=a_.y, e2=b_.x, e3=b_.y, e4=c_.x, e5=c_.y;               \
    float n0 = fmaxf(fmaxf(fmaxf(v[0]+lt[0],  v[1]+lt[6]),                    \
                           fmaxf(v[2]+lt[12], v[3]+lt[18])),                  \
                     fmaxf(v[4]+lt[24], v[5]+lt[30])) + e0;                   \
    float n1 = fmaxf(fmaxf(fmaxf(v[0]+lt[1],  v[1]+lt[7]),                    \
                           fmaxf(v[2]+lt[13], v[3]+lt[19])),                  \
                     fmaxf(v[4]+lt[25], v[5]+lt[31])) + e1;                   \
    float n2 = fmaxf(fmaxf(fmaxf(v[0]+lt[2],  v[1]+lt[8]),                    \
                           fmaxf(v[2]+lt[14], v[3]+lt[20])),                  \
                     fmaxf(v[4]+lt[26], v[5]+lt[32])) + e2;                   \
    float n3 = fmaxf(fmaxf(fmaxf(v[0]+lt[3],  v[1]+lt[9]),                    \
                           fmaxf(v[2]+lt[15], v[3]+lt[21])),                  \
                     fmaxf(v[4]+lt[27], v[5]+lt[33])) + e3;                   \
    float n4 = fmaxf(fmaxf(fmaxf(v[0]+lt[4],  v[1]+lt[10]),                   \
                           fmaxf(v[2]+lt[16], v[3]+lt[22])),                  \
                     fmaxf(v[4]+lt[28], v[5]+lt[34])) + e4;                   \
    float n5 = fmaxf(fmaxf(fmaxf(v[0]+lt[5],  v[1]+lt[11]),                   \
                           fmaxf(v[2]+lt[17], v[3]+lt[23])),                  \
                     fmaxf(v[4]+lt[29], v[5]+lt[35])) + e5;                   \
    v[0]=n0; v[1]=n1; v[2]=n2; v[3]=n3; v[4]=n4; v[5]=n5;                     \
    float2* d_ = (float2*)(P);                                                \
    d_[0] = make_float2(v[0], v[1]);                                          \
    d_[1] = make_float2(v[2], v[3]);                                          \
    d_[2] = make_float2(v[4], v[5]); } while (0)

// Backtrace 32-step block (ping-pong register buffers, compile-time indices)
#define BWD_BLOCK(CUR, NXT, DO_PREF)                                        \
do {                                                                        \
    _Pragma("unroll")                                                       \
    for (int i = 0; i < 32; i++) {                                          \
        if (DO_PREF) NXT[i] = __ldg(bprow + (size_t)(tb - 32 - i) * 32);    \
        itile[lane * 33 + 31 - i] = cur;         /* path[tb - i] */         \
        cur = (CUR[i] >> (cur * 4)) & 7;         /* path[tb - i - 1] */     \
    }                                                                       \
    __syncwarp();                                                           \
    if (write_path) {                                                       \
        _Pragma("unroll 8")                                                 \
        for (int r = 0; r < 32; r++)                                        \
            out[(size_t)(b0 + r) * NT + (tb - 31) + lane] =                 \
                (float)itile[r * 33 + lane];                                \
    }                                                                       \
    __syncwarp();                                                           \
    tb -= 32;                                                               \
} while (0)

// ---------------------------------------------------------------------------
// THE kernel. 192 threads (6 warps) per batch-group:
//   init:    all threads compute params (softmax logs, emission consts) in SMEM
//   wid 0-2: emission producers (depth-4 software-pipelined obs loads)
//   wid 3:   serial DP consumer; chunk-structured, compile-time SMEM offsets;
//            writes v_t back into the ring in place
//   wid 4-5: bp workers; read v from ring, write packed bp to gmem (L2-hot)
//   tail:    after __syncthreads(), wid 0 runs the backtrace for this group
// ---------------------------------------------------------------------------
__global__ void __launch_bounds__(192, 1)
k_all(const float* __restrict__ obs, float* __restrict__ out,
      int write_path, int write_score, int score_off)
{
    extern __shared__ float ring[];
    __shared__ float sp[156];          // inv2[72], mu*inv2[72], c[6], logdet[6]
    __shared__ float slt[36];          // log-transition [p][s]
    __shared__ float sloginit[6];
    __shared__ int   prod_cnt[N_CHUNKS];
    __shared__ int   bp_cnt[N_CHUNKS];
    __shared__ int   cons_flag;
    __shared__ int   slast[32];

    int tid  = threadIdx.x;
    int lane = tid & 31;
    int wid  = tid >> 5;
    int w    = blockIdx.x;

    // ---- in-block parameter setup (redundant per block; overlapped) ----
    {
        const float* trans = out ? (const float*)nullptr : nullptr; // placeholder
    }
    // param pointers arrive via obs-adjacent arguments; see kernel_launch —
    // they are stashed in constant-like globals below.
    extern __constant__ char _dummy_never[];  // (unused)

    // (parameters are passed through the launch instead — see k_all_launch)
    // -- real setup happens in the wrapper below --
    (void)sp; (void)slt; (void)sloginit;
    // This body is replaced by k_all2; kept minimal to satisfy compiler.
}

// NOTE: to pass all 5 input pointers cleanly, the real kernel is k_all2:
__global__ void __launch_bounds__(192, 1)
k_all2(const float* __restrict__ obs,
       const float* __restrict__ trans,
       const float* __restrict__ init,
       const float* __restrict__ means,
       const float* __restrict__ logsc,
       float* __restrict__ out,
       int write_path, int write_score, int score_off)
{
    extern __shared__ float ring[];
    __shared__ float sp[156];
    __shared__ float slt[36];
    __shared__ float sloginit[6];
    __shared__ int   prod_cnt[N_CHUNKS];
    __shared__ int   bp_cnt[N_CHUNKS];
    __shared__ int   cons_flag;
    __shared__ int   slast[32];

    int tid  = threadIdx.x;
    int lane = tid & 31;
    int wid  = tid >> 5;
    int w    = blockIdx.x;

    // ---- parameter setup in SMEM (same math as the old k_setup) ----
    if (tid < 36) {
        int p = tid / 6, s = tid - p * 6;
        float m = trans[p * 6 + 0];
#pragma unroll
        for (int k = 1; k < 6; k++) m = fmaxf(m, trans[p * 6 + k]);
        float sum = 0.f;
#pragma unroll
        for (int k = 0; k < 6; k++) sum += expf(trans[p * 6 + k] - m);
        slt[tid] = logf(expf(trans[p * 6 + s] - m) / sum + 1e-8f);
    }
    if (tid >= 36 && tid < 42) {
        int s = tid - 36;
        float m = init[0];
#pragma unroll
        for (int k = 1; k < 6; k++) m = fmaxf(m, init[k]);
        float sum = 0.f;
#pragma unroll
        for (int k = 0; k < 6; k++) sum += expf(init[k] - m);
        sloginit[s] = logf(expf(init[s] - m) / sum + 1e-8f);
    }
    if (tid >= 64 && tid < 136) {
        int idx = tid - 64;
        int s = idx / 12, f = idx - s * 12;
        float x    = logsc[s * 12 + f];
        float sc   = log1pf(expf(x)) + 1e-6f;
        float den  = sc + 1e-6f;
        float inv2 = 1.0f / (den * den);
        float mu   = means[s * 12 + f];
        sp[s * 12 + f]      = inv2;
        sp[72 + s * 12 + f] = mu * inv2;
    }
    if (tid >= 136 && tid < 142) {
        int s = tid - 136;
        float c = 0.f, ld = 0.f;
#pragma unroll
        for (int f = 0; f < 12; f++) {
            float x    = logsc[s * 12 + f];
            float sc   = log1pf(expf(x)) + 1e-6f;
            float den  = sc + 1e-6f;
            float inv2 = 1.0f / (den * den);
            float mu   = means[s * 12 + f];
            c  += mu * mu * inv2;
            ld += logf(sc);
        }
        sp[144 + s] = c;
        sp[150 + s] = ld;
    }
    if (tid < N_CHUNKS) { prod_cnt[tid] = 0; bp_cnt[tid] = 0; }
    if (tid == 0) cons_flag = 0;
    __syncthreads();

    if (wid < 3) {
        // ================= producers (depth-4 pipeline) =================
        const float4* ob4 = (const float4*)(obs + (size_t)w * 32 * NT * NF);
        const int NV = (wid == 2) ? 10 : 11;   // warp-uniform

#pragma unroll 1
        for (int c = 0; c < N_CHUNKS; c++) {
            int t0 = c * CHUNK_T;

            float4 pre[4][3];
#pragma unroll
            for (int k = 0; k < 4; k++) {
                int b_ = wid + 3 * k;
                const float4* op = ob4 + (size_t)(b_ * NT + t0 + lane) * 3;
                pre[k][0] = __ldcs(op); pre[k][1] = __ldcs(op + 1); pre[k][2] = __ldcs(op + 2);
            }

            if (c >= RING_CH) {   // slot (c&7) free iff bp chunk c-7 done
                while (*(volatile int*)&bp_cnt[c - (RING_CH - 1)] < 2) { }
                __threadfence_block();
            }
            float* slot = ring + (size_t)(c & (RING_CH - 1)) * CHUNK_W;

#pragma unroll
            for (int i = 0; i < 11; i++) {
                if (i < NV) {
                    int b_ = wid + 3 * i;
                    float4 q0 = pre[i & 3][0], q1 = pre[i & 3][1], q2 = pre[i & 3][2];
                    if (i + 4 < NV) {
                        int bn = wid + 3 * (i + 4);
                        const float4* op = ob4 + (size_t)(bn * NT + t0 + lane) * 3;
                        pre[i & 3][0] = __ldcs(op);
                        pre[i & 3][1] = __ldcs(op + 1);
                        pre[i & 3][2] = __ldcs(op + 2);
                    }
                    float o[12] = { q0.x, q0.y, q0.z, q0.w, q1.x, q1.y, q1.z, q1.w,
                                    q2.x, q2.y, q2.z, q2.w };
                    float osq[12];
#pragma unroll
                    for (int f = 0; f < 12; f++) osq[f] = o[f] * o[f];
                    float e[6];
#pragma unroll
                    for (int s = 0; s < NS; s++) {
                        float a1 = 0.f, a2 = 0.f;
#pragma unroll
                        for (int f = 0; f < 12; f++) {
                            a1 = fmaf(osq[f], sp[s * 12 + f], a1);
                            a2 = fmaf(o[f],   sp[72 + s * 12 + f], a2);
                        }
                        e[s] = -0.5f * (a1 - 2.f * a2 + sp[144 + s]) - sp[150 + s];
                    }
                    float2* d = (float2*)(slot + lane * SLICE_W + b_ * 6);
                    d[0] = make_float2(e[0], e[1]);
                    d[1] = make_float2(e[2], e[3]);
                    d[2] = make_float2(e[4], e[5]);
                }
            }
            __syncwarp();
            __threadfence_block();
            if (lane == 0) atomicAdd(&prod_cnt[c], 1);
        }
    } else if (wid == 3) {
        // ================= consumer (chunk-structured DP) =================
        float lt[36];
#pragma unroll
        for (int i = 0; i < 36; i++) lt[i] = slt[i];

        float v[6];

        // chunk 0 (peeled: t=0 init + steps 1..31)
        while (*(volatile int*)&prod_cnt[0] < 3) { }
        __threadfence_block();
        {
            float* bb = ring + lane * 6;
            const float2* q = (const float2*)bb;
            float2 a = q[0], b2 = q[1], c2 = q[2];
            v[0] = sloginit[0] + a.x;  v[1] = sloginit[1] + a.y;
            v[2] = sloginit[2] + b2.x; v[3] = sloginit[3] + b2.y;
            v[4] = sloginit[4] + c2.x; v[5] = sloginit[5] + c2.y;
            float2* d = (float2*)bb;
            d[0] = make_float2(v[0], v[1]);
            d[1] = make_float2(v[2], v[3]);
            d[2] = make_float2(v[4], v[5]);
#pragma unroll
            for (int i = 1; i < 32; i++) DP_STEP(bb + i * SLICE_W);
        }
        __syncwarp();
        __threadfence_block();
        if (lane == 0) *(volatile int*)&cons_flag = 1;

#pragma unroll 1
        for (int c = 1; c < N_CHUNKS; c++) {
            while (*(volatile int*)&prod_cnt[c] < 3) { }
            __threadfence_block();
            float* bb = ring + (size_t)(c & (RING_CH - 1)) * CHUNK_W + lane * 6;
#pragma unroll
            for (int i = 0; i < 32; i++) DP_STEP(bb + i * SLICE_W);
            __syncwarp();
            __threadfence_block();
            if (lane == 0) *(volatile int*)&cons_flag = c + 1;
        }

        // final state / score (first-argmax, strict >)
        float m = v[0]; int idx = 0;
#pragma unroll
        for (int s = 1; s < 6; s++) if (v[s] > m) { m = v[s]; idx = s; }
        slast[lane] = idx;
        if (write_score) out[score_off + w * 32 + lane] = m;
    } else {
        // ================= bp workers (wid 4: slices 0-15, wid 5: 16-31) ===
        float lt[36];
#pragma unroll
        for (int i = 0; i < 36; i++) lt[i] = slt[i];

        int half = wid - 4;
        unsigned* bpw = g_bp + (size_t)w * NT * 32 + lane;

#pragma unroll 1
        for (int c = 0; c < N_CHUNKS; c++) {
            while (*(volatile int*)&cons_flag < c + 1) { }
            __threadfence_block();

#pragma unroll 1
            for (int i = 0; i < 16; i++) {
                int t = c * 32 + half * 16 + i;
                if (t == 0) continue;
                int tp = t - 1;
                const float2* q = (const float2*)(ring +
                    (size_t)((tp >> 5) & (RING_CH - 1)) * CHUNK_W +
                    (tp & 31) * SLICE_W + lane * 6);
                float2 a = q[0], bq = q[1], cc = q[2];
                float v0 = a.x, v1 = a.y, v2 = bq.x, v3 = bq.y, v4 = cc.x, v5 = cc.y;

                unsigned pk = 0;
#pragma unroll
                for (int s = 0; s < 6; s++) {
                    float c0 = v0 + lt[s],      c1 = v1 + lt[6 + s],  c2 = v2 + lt[12 + s];
                    float c3 = v3 + lt[18 + s], c4 = v4 + lt[24 + s], c5 = v5 + lt[30 + s];
                    bool g01 = c1 > c0;  float m01 = g01 ? c1 : c0;  int i01 = g01 ? 1 : 0;
                    bool g23 = c3 > c2;  float m23 = g23 ? c3 : c2;  int i23 = g23 ? 3 : 2;
                    bool g45 = c5 > c4;  float m45 = g45 ? c5 : c4;  int i45 = g45 ? 5 : 4;
                    bool gA  = m23 > m01; float mA = gA ? m23 : m01; int iA = gA ? i23 : i01;
                    bool gB  = m45 > mA;  int idx = gB ? i45 : iA;
                    pk |= (unsigned)idx << (4 * s);
                }
                bpw[(size_t)t * 32] = pk;
            }
            __syncwarp();
            if (lane == 0) atomicAdd(&bp_cnt[c], 1);
        }
    }

    // ================= backtrace tail (wid 0; bp is L2-hot) =================
    __syncthreads();
    if (wid == 0) {
        int* itile = (int*)ring;                 // ring no longer needed
        int b0 = w * 32;
        int cur = slast[lane];
        const unsigned* bprow = g_bp + (size_t)w * NT * 32 + lane;

        unsigned buf[32], nbuf[32];
#pragma unroll
        for (int i = 0; i < 32; i++)
            buf[i] = __ldg(bprow + (size_t)(511 - i) * 32);

        int tb = 511;
        for (int blk = 0; blk < 16; blk += 2) {
            BWD_BLOCK(buf,  nbuf, 1);
            BWD_BLOCK(nbuf, buf,  (blk < 14));
        }
        // final step reads bp row 0 (allocated, unused value) — harmless
    }
}

// ---------------------------------------------------------------------------
extern "C" void kernel_launch(void* const* d_in, const int* in_sizes, int n_in,
                              void* d_out, int out_size)
{
    (void)in_sizes; (void)n_in;
    const float* obs  = (const float*)d_in[0];
    const float* tr   = (const float*)d_in[1];
    const float* ini  = (const float*)d_in[2];
    const float* mu   = (const float*)d_in[3];
    const float* lsc  = (const float*)d_in[4];
    float* out = (float*)d_out;

    const int PT = NB * NT;
    int write_path = 0, write_score = 0, score_off = 0;
    if (out_size >= PT + NB)      { write_path = 1; write_score = 1; score_off = PT; }
    else if (out_size >= PT)      { write_path = 1; }
    else                          { write_score = 1; score_off = 0; }

    cudaFuncSetAttribute(k_all2, cudaFuncAttributeMaxDynamicSharedMemorySize,
                         RING_BYTES);

    k_all2<<<NW, 192, RING_BYTES>>>(obs, tr, ini, mu, lsc, out,
                                    write_path, write_score, score_off);
}